// round 1
// baseline (speedup 1.0000x reference)
#include <cuda_runtime.h>
#include <cuda_bf16.h>
#include <cstdint>

#define NB    16384
#define LCODE 32
#define DDIM  128
#define NDIAG 100000
#define NPROC 50000
#define NMED  1000

// ---- scratch (static device globals; no allocation) ----
__device__ __nv_bfloat16 g_diagb[NDIAG * DDIM];
__device__ __nv_bfloat16 g_procb[NPROC * DDIM];
__device__ __nv_bfloat16 g_W1b[128 * 256];
__device__ __nv_bfloat16 g_W2b[256 * 256];
__device__ __nv_bfloat16 g_W3b[NMED * 256];
__device__ __nv_bfloat16 g_X[(size_t)NB * 512];
__device__ __nv_bfloat16 g_rep[(size_t)NB * 256];
__device__ __nv_bfloat16 g_h[(size_t)NB * 256];

// ---- fp32 -> bf16 conversion (vectorized) ----
__global__ void convert4_kernel(const float4* __restrict__ in,
                                uint2* __restrict__ out, int n4) {
    int i = blockIdx.x * blockDim.x + threadIdx.x;
    int stride = gridDim.x * blockDim.x;
    for (; i < n4; i += stride) {
        float4 v = in[i];
        __nv_bfloat162 lo, hi;
        lo.x = __float2bfloat16(v.x); lo.y = __float2bfloat16(v.y);
        hi.x = __float2bfloat16(v.z); hi.y = __float2bfloat16(v.w);
        uint2 o;
        o.x = *reinterpret_cast<uint32_t*>(&lo);
        o.y = *reinterpret_cast<uint32_t*>(&hi);
        out[i] = o;
    }
}

// ---- embedding bag: one warp per batch row; X[b] = [emb_d|emb_p|prev_d|prev_p] bf16 ----
__global__ __launch_bounds__(256) void embed_kernel(
    const int* __restrict__ diag, const int* __restrict__ proc,
    const int* __restrict__ pdiag, const int* __restrict__ pproc) {
    int warp = (blockIdx.x * blockDim.x + threadIdx.x) >> 5;
    int lane = threadIdx.x & 31;
    if (warp >= NB) return;

    const int* codes[4] = {diag, proc, pdiag, pproc};
    const __nv_bfloat16* tabs[4] = {g_diagb, g_procb, g_diagb, g_procb};

    #pragma unroll
    for (int bag = 0; bag < 4; bag++) {
        int mycode = codes[bag][warp * LCODE + lane];
        float4 acc = make_float4(0.f, 0.f, 0.f, 0.f);
        #pragma unroll
        for (int j = 0; j < LCODE; j++) {
            int c = __shfl_sync(0xffffffffu, mycode, j);
            uint2 v = *reinterpret_cast<const uint2*>(tabs[bag] + (size_t)c * DDIM + lane * 4);
            __nv_bfloat162 v0 = *reinterpret_cast<__nv_bfloat162*>(&v.x);
            __nv_bfloat162 v1 = *reinterpret_cast<__nv_bfloat162*>(&v.y);
            float2 f0 = __bfloat1622float2(v0);
            float2 f1 = __bfloat1622float2(v1);
            acc.x += f0.x; acc.y += f0.y; acc.z += f1.x; acc.w += f1.y;
        }
        __nv_bfloat162 p0, p1;
        p0.x = __float2bfloat16(acc.x); p0.y = __float2bfloat16(acc.y);
        p1.x = __float2bfloat16(acc.z); p1.y = __float2bfloat16(acc.w);
        uint2 o;
        o.x = *reinterpret_cast<uint32_t*>(&p0);
        o.y = *reinterpret_cast<uint32_t*>(&p1);
        *reinterpret_cast<uint2*>(g_X + (size_t)warp * 512 + bag * 128 + lane * 4) = o;
    }
}

// ---- bf16 mma GEMM: C[M,N] = act(A[M,K(lda)] @ W[N,K]^T + bias) ----
// BM=128 BN=128 BK=32, 256 thr (8 warps as 2x4), warp tile 64x32 via m16n8k16.
// Smem row stride = 40 halves (80B): fragment LDS (4B, quad-grouped) is bank-conflict-free.
#define MMA_BF16(d, a, b)                                                     \
    asm volatile(                                                             \
        "mma.sync.aligned.m16n8k16.row.col.f32.bf16.bf16.f32 "               \
        "{%0,%1,%2,%3}, {%4,%5,%6,%7}, {%8,%9}, {%0,%1,%2,%3};\n"            \
        : "+f"(d[0]), "+f"(d[1]), "+f"(d[2]), "+f"(d[3])                      \
        : "r"(a[0]), "r"(a[1]), "r"(a[2]), "r"(a[3]), "r"(b[0]), "r"(b[1]))

template <int ACT, typename OutT>  // ACT: 0=none 1=relu 2=sigmoid
__global__ __launch_bounds__(256) void gemm_kernel(
    const __nv_bfloat16* __restrict__ A, int lda,
    const __nv_bfloat16* __restrict__ W,      // [N,K], ld = K
    const float* __restrict__ bias,
    OutT* __restrict__ C, int ldc, int N, int K) {
    __shared__ __nv_bfloat16 As[128 * 40];
    __shared__ __nv_bfloat16 Bs[128 * 40];

    const int tid = threadIdx.x;
    const int warp = tid >> 5, lane = tid & 31;
    const int wm = warp >> 2, wn = warp & 3;     // 2 x 4 warp grid
    const int g = lane >> 2, tq = lane & 3;
    const int m0 = blockIdx.x * 128;
    const int n0 = blockIdx.y * 128;

    float acc[4][4][4];
    #pragma unroll
    for (int mt = 0; mt < 4; mt++)
        #pragma unroll
        for (int nt = 0; nt < 4; nt++)
            #pragma unroll
            for (int i = 0; i < 4; i++) acc[mt][nt][i] = 0.f;

    for (int k0 = 0; k0 < K; k0 += 32) {
        // stage A tile (128x32) and B tile (128x32 of W rows)
        #pragma unroll
        for (int r = 0; r < 2; r++) {
            int idx = tid + r * 256;
            int row = idx >> 2, c = idx & 3;
            uint4 v = *reinterpret_cast<const uint4*>(
                A + (size_t)(m0 + row) * lda + k0 + c * 8);
            *reinterpret_cast<uint4*>(As + row * 40 + c * 8) = v;
        }
        #pragma unroll
        for (int r = 0; r < 2; r++) {
            int idx = tid + r * 256;
            int row = idx >> 2, c = idx & 3;
            uint4 v = make_uint4(0u, 0u, 0u, 0u);
            if (n0 + row < N)
                v = *reinterpret_cast<const uint4*>(
                    W + (size_t)(n0 + row) * K + k0 + c * 8);
            *reinterpret_cast<uint4*>(Bs + row * 40 + c * 8) = v;
        }
        __syncthreads();

        const uint32_t* As32 = reinterpret_cast<const uint32_t*>(As);
        const uint32_t* Bs32 = reinterpret_cast<const uint32_t*>(Bs);
        #pragma unroll
        for (int kk = 0; kk < 2; kk++) {
            const int kb = kk * 16;
            uint32_t af[4][4], bf[4][2];
            #pragma unroll
            for (int mt = 0; mt < 4; mt++) {
                int mrow = wm * 64 + mt * 16 + g;
                int base = mrow * 20 + (kb >> 1) + tq;   // u32 units (stride 40 halves)
                af[mt][0] = As32[base];
                af[mt][1] = As32[base + 160];            // +8 rows
                af[mt][2] = As32[base + 4];              // +8 halves in k
                af[mt][3] = As32[base + 164];
            }
            #pragma unroll
            for (int nt = 0; nt < 4; nt++) {
                int nrow = wn * 32 + nt * 8 + g;
                int base = nrow * 20 + (kb >> 1) + tq;
                bf[nt][0] = Bs32[base];
                bf[nt][1] = Bs32[base + 4];
            }
            #pragma unroll
            for (int mt = 0; mt < 4; mt++)
                #pragma unroll
                for (int nt = 0; nt < 4; nt++) MMA_BF16(acc[mt][nt], af[mt], bf[nt]);
        }
        __syncthreads();
    }

    // epilogue: bias + activation + store
    #pragma unroll
    for (int mt = 0; mt < 4; mt++) {
        int row0 = m0 + wm * 64 + mt * 16 + g;
        #pragma unroll
        for (int nt = 0; nt < 4; nt++) {
            int col = n0 + wn * 32 + nt * 8 + 2 * tq;
            if (col < N) {   // col even, N even => pair never straddles
                float bx = __ldg(bias + col), by = __ldg(bias + col + 1);
                float v0 = acc[mt][nt][0] + bx, v1 = acc[mt][nt][1] + by;
                float v2 = acc[mt][nt][2] + bx, v3 = acc[mt][nt][3] + by;
                if (ACT == 1) {
                    v0 = fmaxf(v0, 0.f); v1 = fmaxf(v1, 0.f);
                    v2 = fmaxf(v2, 0.f); v3 = fmaxf(v3, 0.f);
                } else if (ACT == 2) {
                    v0 = 1.f / (1.f + __expf(-v0)); v1 = 1.f / (1.f + __expf(-v1));
                    v2 = 1.f / (1.f + __expf(-v2)); v3 = 1.f / (1.f + __expf(-v3));
                }
                if (sizeof(OutT) == 2) {  // bf16 output
                    __nv_bfloat162 p0, p1;
                    p0.x = __float2bfloat16(v0); p0.y = __float2bfloat16(v1);
                    p1.x = __float2bfloat16(v2); p1.y = __float2bfloat16(v3);
                    *reinterpret_cast<uint32_t*>((__nv_bfloat16*)C + (size_t)row0 * ldc + col) =
                        *reinterpret_cast<uint32_t*>(&p0);
                    *reinterpret_cast<uint32_t*>((__nv_bfloat16*)C + (size_t)(row0 + 8) * ldc + col) =
                        *reinterpret_cast<uint32_t*>(&p1);
                } else {                  // fp32 output
                    float2 f0 = make_float2(v0, v1), f1 = make_float2(v2, v3);
                    *reinterpret_cast<float2*>((float*)C + (size_t)row0 * ldc + col) = f0;
                    *reinterpret_cast<float2*>((float*)C + (size_t)(row0 + 8) * ldc + col) = f1;
                }
            }
        }
    }
}

extern "C" void kernel_launch(void* const* d_in, const int* in_sizes, int n_in,
                              void* d_out, int out_size) {
    const int* diag  = (const int*)d_in[0];
    const int* proc  = (const int*)d_in[1];
    const int* pdiag = (const int*)d_in[2];
    const int* pproc = (const int*)d_in[3];
    const float* diag_emb = (const float*)d_in[4];
    const float* proc_emb = (const float*)d_in[5];
    const float* W1 = (const float*)d_in[6];
    const float* b1 = (const float*)d_in[7];
    const float* W2 = (const float*)d_in[8];
    const float* b2 = (const float*)d_in[9];
    const float* W3 = (const float*)d_in[10];
    const float* b3 = (const float*)d_in[11];
    float* out = (float*)d_out;

    __nv_bfloat16 *p_diagb, *p_procb, *p_W1b, *p_W2b, *p_W3b, *p_X, *p_rep, *p_h;
    cudaGetSymbolAddress((void**)&p_diagb, g_diagb);
    cudaGetSymbolAddress((void**)&p_procb, g_procb);
    cudaGetSymbolAddress((void**)&p_W1b, g_W1b);
    cudaGetSymbolAddress((void**)&p_W2b, g_W2b);
    cudaGetSymbolAddress((void**)&p_W3b, g_W3b);
    cudaGetSymbolAddress((void**)&p_X, g_X);
    cudaGetSymbolAddress((void**)&p_rep, g_rep);
    cudaGetSymbolAddress((void**)&p_h, g_h);

    auto cvt = [&](const float* src, __nv_bfloat16* dst, int n) {
        int n4 = n / 4;
        int grid = (n4 + 255) / 256;
        if (grid > 16384) grid = 16384;
        convert4_kernel<<<grid, 256>>>((const float4*)src, (uint2*)dst, n4);
    };
    cvt(diag_emb, p_diagb, NDIAG * DDIM);
    cvt(proc_emb, p_procb, NPROC * DDIM);
    cvt(W1, p_W1b, 128 * 256);
    cvt(W2, p_W2b, 256 * 256);
    cvt(W3, p_W3b, NMED * 256);

    // embeddings: 16384 rows, 1 warp each
    embed_kernel<<<NB / 8, 256>>>(diag, proc, pdiag, pproc);

    // GEMM1 (block-diag W1 as two strided GEMMs): rep[:, :128] and rep[:, 128:]
    gemm_kernel<0, __nv_bfloat16><<<dim3(NB / 128, 1), 256>>>(
        p_X, 512, p_W1b, b1, p_rep, 256, 128, 256);
    gemm_kernel<0, __nv_bfloat16><<<dim3(NB / 128, 1), 256>>>(
        p_X + 256, 512, p_W1b, b1, p_rep + 128, 256, 128, 256);
    // GEMM2: h = relu(rep @ W2^T + b2)
    gemm_kernel<1, __nv_bfloat16><<<dim3(NB / 128, 2), 256>>>(
        p_rep, 256, p_W2b, b2, p_h, 256, 256, 256);
    // GEMM3: out = sigmoid(h @ W3^T + b3), fp32 output
    gemm_kernel<2, float><<<dim3(NB / 128, 8), 256>>>(
        p_h, 256, p_W3b, b3, out, NMED, NMED, 256);
}